// round 4
// baseline (speedup 1.0000x reference)
#include <cuda_runtime.h>
#include <cuda_bf16.h>

// FrozenBNBStableEmbedding fused gather+dequant+LayerNorm.
// R4: 16x-replicated code table in smem to kill LDS bank conflicts
// (random-index lookups were ~4-way conflicted = 2/3 of L1 traffic).

#define D    1024
#define TPB  256
#define TOK  16          // tokens per CTA
#define REP  16          // table replication factor
#define EPS  1e-5f

__global__ __launch_bounds__(TPB) void emb_ln_kernel(
    const int*   __restrict__ x,
    const int*   __restrict__ w,
    const float* __restrict__ absmax,
    const float* __restrict__ code,
    const float* __restrict__ lnw,
    const float* __restrict__ lnb,
    float*       __restrict__ out,
    int n_tokens)
{
    __shared__ float s_code[256 * REP];   // s_code[idx*REP + (lane&15)]
    __shared__ int   s_rows[TOK];
    __shared__ float s_part[2][2][8];     // [buf][sum|sq][warp]

    const int tid  = threadIdx.x;
    const int warp = tid >> 5;
    const int lane = tid & 31;
    const int base = blockIdx.x * TOK;

    // Fill replicated table: thread tid owns entry tid, writes 16 copies
    {
        const float c = code[tid];
        float4 cv = make_float4(c, c, c, c);
        float4* dst = reinterpret_cast<float4*>(&s_code[tid * REP]);
        dst[0] = cv; dst[1] = cv; dst[2] = cv; dst[3] = cv;
    }
    if (tid < TOK) {
        int idx = base + tid;
        s_rows[tid] = (idx < n_tokens) ? x[idx] : 0;
    }

    // LN params in registers for all TOK tokens
    const float4 gw = __ldg(&reinterpret_cast<const float4*>(lnw)[tid]);
    const float4 gb = __ldg(&reinterpret_cast<const float4*>(lnb)[tid]);
    __syncthreads();

    // Per-thread slot in the replicated table (conflict-light)
    const float* tab = &s_code[lane & (REP - 1)];

    // Prime pipeline: token 0
    int   row   = s_rows[0];
    int4  q     = __ldg(&reinterpret_cast<const int4*>(w + (long long)row * D)[tid]);
    float scale = __ldg(&absmax[row >> 2]);

    const int ntok = min(TOK, n_tokens - base);

    for (int t = 0; t < ntok; ++t) {
        // Prefetch token t+1
        int4  qn;
        float scn = 0.0f;
        if (t + 1 < ntok) {
            int rn = s_rows[t + 1];
            qn  = __ldg(&reinterpret_cast<const int4*>(w + (long long)rn * D)[tid]);
            scn = __ldg(&absmax[rn >> 2]);
        }

        float v0 = tab[(q.x & 255) * REP] * scale;
        float v1 = tab[(q.y & 255) * REP] * scale;
        float v2 = tab[(q.z & 255) * REP] * scale;
        float v3 = tab[(q.w & 255) * REP] * scale;

        float sum = v0 + v1 + v2 + v3;
        float sq  = v0*v0 + v1*v1 + v2*v2 + v3*v3;

        #pragma unroll
        for (int off = 16; off > 0; off >>= 1) {
            sum += __shfl_xor_sync(0xFFFFFFFFu, sum, off);
            sq  += __shfl_xor_sync(0xFFFFFFFFu, sq,  off);
        }
        const int buf = t & 1;
        if (lane == 0) { s_part[buf][0][warp] = sum; s_part[buf][1][warp] = sq; }
        __syncthreads();

        // Every warp reduces the 8 partials redundantly (no second barrier)
        float s = (lane < 8) ? s_part[buf][0][lane] : 0.0f;
        float z = (lane < 8) ? s_part[buf][1][lane] : 0.0f;
        #pragma unroll
        for (int off = 4; off > 0; off >>= 1) {
            s += __shfl_xor_sync(0xFFFFFFFFu, s, off);
            z += __shfl_xor_sync(0xFFFFFFFFu, z, off);
        }
        const float mean = __shfl_sync(0xFFFFFFFFu, s, 0) * (1.0f / D);
        const float msq  = __shfl_sync(0xFFFFFFFFu, z, 0) * (1.0f / D);
        const float rstd = rsqrtf(msq - mean * mean + EPS);

        float4 o;
        o.x = (v0 - mean) * rstd * gw.x + gb.x;
        o.y = (v1 - mean) * rstd * gw.y + gb.y;
        o.z = (v2 - mean) * rstd * gw.z + gb.z;
        o.w = (v3 - mean) * rstd * gw.w + gb.w;

        // Streaming store: keep L2 capacity for weight rows
        __stcs(&reinterpret_cast<float4*>(out)[(long long)(base + t) * (D / 4) + tid], o);

        q     = qn;
        scale = scn;
    }
}

extern "C" void kernel_launch(void* const* d_in, const int* in_sizes, int n_in,
                              void* d_out, int out_size)
{
    const int*   x      = (const int*)d_in[0];
    const int*   w      = (const int*)d_in[1];
    const float* absmax = (const float*)d_in[2];
    const float* code   = (const float*)d_in[3];
    const float* lnw    = (const float*)d_in[4];
    const float* lnb    = (const float*)d_in[5];
    float*       out    = (float*)d_out;

    const int n_tokens = in_sizes[0];                 // 16384
    const int grid = (n_tokens + TOK - 1) / TOK;      // 1024
    emb_ln_kernel<<<grid, TPB>>>(x, w, absmax, code, lnw, lnb, out, n_tokens);
}

// round 5
// speedup vs baseline: 1.5008x; 1.5008x over previous
#include <cuda_runtime.h>
#include <cuda_bf16.h>

// FrozenBNBStableEmbedding fused gather+dequant+LayerNorm.
// R5: one WARP per token (32 elems/lane), warp-shfl reduction only —
// no per-token barriers, MLP=8 on weight loads, fewer instrs/elem.

#define D    1024
#define REP  16          // code-table replication
#define TPW  2           // tokens per warp
#define EPS  1e-5f

__global__ __launch_bounds__(256) void emb_ln_kernel(
    const int*   __restrict__ x,
    const int*   __restrict__ w,
    const float* __restrict__ absmax,
    const float* __restrict__ code,
    const float* __restrict__ lnw,
    const float* __restrict__ lnb,
    float*       __restrict__ out,
    int n_tokens)
{
    __shared__ float  s_code[256 * REP];  // s_code[idx*REP + slot]
    __shared__ float4 s_lnw[256];
    __shared__ float4 s_lnb[256];

    const int tid  = threadIdx.x;
    const int warp = tid >> 5;
    const int lane = tid & 31;

    // Fill replicated code table + LN params (once per CTA)
    {
        const float c = code[tid];
        float4 cv = make_float4(c, c, c, c);
        float4* dst = reinterpret_cast<float4*>(&s_code[tid * REP]);
        dst[0] = cv; dst[1] = cv; dst[2] = cv; dst[3] = cv;
        s_lnw[tid] = __ldg(&reinterpret_cast<const float4*>(lnw)[tid]);
        s_lnb[tid] = __ldg(&reinterpret_cast<const float4*>(lnb)[tid]);
    }
    __syncthreads();

    const float* tab = &s_code[lane & (REP - 1)];
    const int warp_g = blockIdx.x * 8 + warp;

    #pragma unroll
    for (int t = 0; t < TPW; ++t) {
        const int tok = warp_g * TPW + t;
        if (tok >= n_tokens) break;

        const int   row   = __ldg(&x[tok]);
        const float scale = __ldg(&absmax[row >> 2]);
        const int4* wrow  = reinterpret_cast<const int4*>(w + (long long)row * D);

        // 8 independent 16B loads: MLP = 8
        int4 q[8];
        #pragma unroll
        for (int i = 0; i < 8; ++i)
            q[i] = __ldg(&wrow[i * 32 + lane]);

        float v[32];
        float sum = 0.0f, sq = 0.0f;
        #pragma unroll
        for (int i = 0; i < 8; ++i) {
            float a = tab[(q[i].x & 255) * REP] * scale;
            float b = tab[(q[i].y & 255) * REP] * scale;
            float c = tab[(q[i].z & 255) * REP] * scale;
            float d = tab[(q[i].w & 255) * REP] * scale;
            v[i*4+0] = a; v[i*4+1] = b; v[i*4+2] = c; v[i*4+3] = d;
            sum += a + b + c + d;
            sq  += a*a + b*b + c*c + d*d;
        }

        // Warp-level reduction (butterfly leaves total in every lane)
        #pragma unroll
        for (int off = 16; off > 0; off >>= 1) {
            sum += __shfl_xor_sync(0xFFFFFFFFu, sum, off);
            sq  += __shfl_xor_sync(0xFFFFFFFFu, sq,  off);
        }
        const float mean = sum * (1.0f / D);
        const float rstd = rsqrtf(sq * (1.0f / D) - mean * mean + EPS);

        float4* orow = reinterpret_cast<float4*>(out) + (long long)tok * (D / 4);
        #pragma unroll
        for (int i = 0; i < 8; ++i) {
            const float4 gw = s_lnw[i * 32 + lane];
            const float4 gb = s_lnb[i * 32 + lane];
            float4 o;
            o.x = (v[i*4+0] - mean) * rstd * gw.x + gb.x;
            o.y = (v[i*4+1] - mean) * rstd * gw.y + gb.y;
            o.z = (v[i*4+2] - mean) * rstd * gw.z + gb.z;
            o.w = (v[i*4+3] - mean) * rstd * gw.w + gb.w;
            __stcs(&orow[i * 32 + lane], o);
        }
    }
}

extern "C" void kernel_launch(void* const* d_in, const int* in_sizes, int n_in,
                              void* d_out, int out_size)
{
    const int*   x      = (const int*)d_in[0];
    const int*   w      = (const int*)d_in[1];
    const float* absmax = (const float*)d_in[2];
    const float* code   = (const float*)d_in[3];
    const float* lnw    = (const float*)d_in[4];
    const float* lnb    = (const float*)d_in[5];
    float*       out    = (float*)d_out;

    const int n_tokens = in_sizes[0];                     // 16384
    const int tokens_per_cta = 8 * TPW;                   // 16
    const int grid = (n_tokens + tokens_per_cta - 1) / tokens_per_cta;  // 1024
    emb_ln_kernel<<<grid, 256>>>(x, w, absmax, code, lnw, lnb, out, n_tokens);
}